// round 11
// baseline (speedup 1.0000x reference)
#include <cuda_runtime.h>
#include <cuda_fp16.h>
#include <cstdint>

#define NB 8
#define NC 64
#define NH 256
#define NW 512
#define NK 9
#define HW (NH * NW)                // 131,072
#define BHW (NB * NH * NW)          // 1,048,576
#define NROWS (NB * NH)             // 2048
#define NBLK 592                    // 148 SMs x 4 blocks

typedef unsigned long long ull;

// Scratch: P[k][b][y][x] = sum_c W[c,k] * F[b,c,y,x]   (fp16: 18.9 MB, L2-resident)
__device__ __half g_P[(size_t)NK * BHW];

// Packed f32x2 FMA (sm_100+): d = a*b + c on two lanes at once.
#define FMA_F32X2(d, a, b, c) \
    asm("fma.rn.f32x2 %0, %1, %2, %3;" : "=l"(d) : "l"(a), "l"(b), "l"(c))

__device__ __forceinline__ void cp16(uint32_t dst, const void* src) {
    asm volatile("cp.async.cg.shared.global [%0], [%1], 16;" :: "r"(dst), "l"(src));
}
__device__ __forceinline__ void cpcommit() {
    asm volatile("cp.async.commit_group;");
}
template <int N> __device__ __forceinline__ void cpwait() {
    asm volatile("cp.async.wait_group %0;" :: "n"(N));
}

// ---------------------------------------------------------------------------
// Pass 1: channel reduction, cp.async-pipelined, PERSISTENT grid.
// 592 blocks (148 SM x 4); each walks rows yb = bid, bid+592, ... with ONE
// continuous flat (row,chunk) pipeline: no per-row prologue/drain, no wave
// boundaries. 3-stage ring (16 KB/stage), 1 barrier per chunk.
// ---------------------------------------------------------------------------
__global__ void __launch_bounds__(256) pass1_kernel(
    const float* __restrict__ feature,   // [B, C, H, W]
    const float* __restrict__ weight)    // [1, C, 3, 3] -> [C, 9]
{
    extern __shared__ float buf[];       // [3 stages][8 ch][512 x] = 49152 B
    __shared__ float4 sw4[NK][NC / 2];   // {w_c,w_c,w_c1,w_c1} per (k, pair)

    const int t = threadIdx.x;

    for (int i = t; i < NK * (NC / 2); i += 256) {
        int k  = i % NK;
        int cc = i / NK;
        float w0 = weight[(2 * cc + 0) * NK + k];
        float w1 = weight[(2 * cc + 1) * NK + k];
        sw4[k][cc] = make_float4(w0, w0, w1, w1);
    }

    const int bid = blockIdx.x;
    const int nr = (NROWS - bid + NBLK - 1) / NBLK;   // 3 or 4 rows
    const int totalflat = nr * 8;

    const uint32_t sbase = (uint32_t)__cvta_generic_to_shared(buf);

    // Fill ring stage (flat%3) with flat's chunk: row rl=flat>>3, chunk flat&7.
#define FILL(flat)                                                            \
    do {                                                                      \
        int _rl = (flat) >> 3, _ck = (flat) & 7;                              \
        int _yb = bid + _rl * NBLK;                                           \
        const float* src0 = feature + (size_t)(_yb / NH) * NC * HW            \
                          + (size_t)(_yb % NH) * NW + (size_t)(_ck * 8) * HW; \
        uint32_t _sb = sbase + (uint32_t)(((flat) % 3) * 16384);              \
        _Pragma("unroll")                                                     \
        for (int i = 0; i < 4; ++i) {                                         \
            int idx = t + i * 256;       /* 0..1023 */                        \
            int cc  = idx >> 7;          /* channel within chunk */           \
            int q   = idx & 127;         /* 16B unit within row */            \
            cp16(_sb + (uint32_t)(cc * 2048 + q * 16),                        \
                 src0 + (size_t)cc * HW + q * 4);                             \
        }                                                                     \
        cpcommit();                                                           \
    } while (0)

    // Prologue: 2 chunks in flight.
    FILL(0);
    FILL(1);

    int flat = 0;
    for (int rl = 0; rl < nr; ++rl) {
        ull acc[NK];
#pragma unroll
        for (int k = 0; k < NK; ++k) acc[k] = 0ull;

#pragma unroll
        for (int ck = 0; ck < 8; ++ck, ++flat) {
            if (flat == totalflat - 1) cpwait<0>();
            else                       cpwait<1>();
            __syncthreads();             // cross-thread visibility of stage

            const float* st = buf + (flat % 3) * 4096;
#pragma unroll
            for (int p = 0; p < 4; ++p) {  // channel pairs within chunk
                ull f0 = *(const ull*)(st + (2 * p + 0) * 512 + 2 * t);
                ull f1 = *(const ull*)(st + (2 * p + 1) * 512 + 2 * t);
                int cidx = ck * 4 + p;     // global pair index 0..31
#pragma unroll
                for (int k = 0; k < NK; ++k) {
                    ulonglong2 wp = *(const ulonglong2*)&sw4[k][cidx];
                    FMA_F32X2(acc[k], f0, wp.x, acc[k]);
                    FMA_F32X2(acc[k], f1, wp.y, acc[k]);
                }
            }
            if (flat + 2 < totalflat) FILL(flat + 2);
        }

        // Store row: thread owns x = {2t, 2t+1}; one 4B half2 store per tap.
        int yb = bid + rl * NBLK;
        size_t pbase = (size_t)yb * NW + 2 * t;
#pragma unroll
        for (int k = 0; k < NK; ++k) {
            float2 v = *(float2*)&acc[k];
            __half2 hv = __floats2half2_rn(v.x, v.y);
            *(__half2*)(g_P + (size_t)k * BHW + pbase) = hv;
        }
    }
#undef FILL
}

// ---------------------------------------------------------------------------
// Pass 2: cyclic-shift gather + 2x2 upsample.
// Key identity: gj[h,w,k] = (w + s[h,k]) % W with s[h,k] = gj[h,0,k], and
// gi[h,w,k] = gi[h,0,k]. So the tap gather is a cyclic row shift.
// Block = (half of row w-range) x h; thread = 8 consecutive w for one b.
// Per block only 18 index ints are read (broadcast).
// ---------------------------------------------------------------------------
__global__ void __launch_bounds__(256, 2) pass2_kernel(
    const int* __restrict__ gi,    // [H, W, 9]
    const int* __restrict__ gj,    // [H, W, 9]
    float* __restrict__ out)       // [B, 1, 2H, 2W]
{
    const int h = blockIdx.y;
    const int t = threadIdx.x;
    const int b  = t >> 5;                         // 0..7
    const int w0 = ((t & 31) + blockIdx.x * 32) * 8;   // 0..504

    const int* ibase_i = gi + (size_t)h * NW * NK;  // row h, w=0
    const int* ibase_j = gj + (size_t)h * NW * NK;

    int ys[NK], ss[NK];
#pragma unroll
    for (int k = 0; k < NK; ++k) ys[k] = ibase_i[k];
#pragma unroll
    for (int k = 0; k < NK; ++k) ss[k] = ibase_j[k];

    float acc[8] = {0.f, 0.f, 0.f, 0.f, 0.f, 0.f, 0.f, 0.f};
#pragma unroll
    for (int k = 0; k < NK; ++k) {
        const unsigned short* row = (const unsigned short*)g_P
            + (size_t)k * BHW + ((size_t)b * NH + ys[k]) * NW;
        int base = w0 + ss[k];
        unsigned short v[8];
#pragma unroll
        for (int j = 0; j < 8; ++j)
            v[j] = row[(base + j) & (NW - 1)];
#pragma unroll
        for (int j = 0; j < 8; ++j)
            acc[j] += __half2float(__ushort_as_half(v[j]));
    }

    // 2x2 upsample: 8 outputs -> 16 floats per row, two rows. Evict-first.
    float* orow = out + ((size_t)b * (2 * NH) + 2 * h) * (2 * NW) + 2 * w0;
#pragma unroll
    for (int i = 0; i < 4; ++i) {
        float4 q = make_float4(acc[2 * i], acc[2 * i],
                               acc[2 * i + 1], acc[2 * i + 1]);
        asm volatile("st.global.cs.v4.f32 [%0], {%1, %2, %3, %4};"
                     :: "l"(orow + 4 * i), "f"(q.x), "f"(q.y), "f"(q.z), "f"(q.w));
        asm volatile("st.global.cs.v4.f32 [%0], {%1, %2, %3, %4};"
                     :: "l"(orow + 2 * NW + 4 * i),
                        "f"(q.x), "f"(q.y), "f"(q.z), "f"(q.w));
    }
}

// ---------------------------------------------------------------------------
// Launch: graph-capturable, allocation-free.
// Inputs (metadata order): feature f32, weight f32, gi i32, gj i32.
// ---------------------------------------------------------------------------
extern "C" void kernel_launch(void* const* d_in, const int* in_sizes, int n_in,
                              void* d_out, int out_size)
{
    const float* feature = (const float*)d_in[0];
    const float* weight  = (const float*)d_in[1];
    const int*   gi      = (const int*)d_in[2];
    const int*   gj      = (const int*)d_in[3];
    float*       out     = (float*)d_out;

    // 48 KB dynamic smem opt-in (idempotent host call).
    static bool attr_set = false;
    if (!attr_set) {
        cudaFuncSetAttribute(pass1_kernel,
                             cudaFuncAttributeMaxDynamicSharedMemorySize, 49152);
        attr_set = true;
    }

    // Pass 1: persistent grid, 592 blocks x 256 threads, 48KB smem
    pass1_kernel<<<NBLK, 256, 49152>>>(feature, weight);
    // Pass 2: grid (2 half-rows, 256 h) x 256 threads
    dim3 g2(2, NH);
    pass2_kernel<<<g2, 256>>>(gi, gj, out);
}